// round 9
// baseline (speedup 1.0000x reference)
#include <cuda_runtime.h>
#include <cuda_fp16.h>
#include <cstdint>

// ======================= problem constants =======================
#define MDIM 32768      // B*S = 16*2048
#define NDIM 4096       // out features
#define KDIM 1024       // in features
#define NBATCH 16

#define BM 128
#define BN 128
#define BK 64                 // halves per K-slab = one SW128 tile col-block
#define NKT 16                // K tiles per output tile
#define STAGES 3

#define TILEB  16384                // one 128x64-half tile, swizzled, contiguous
#define STAGEB (2 * TILEB)          // A + B = 32768
#define SMEM_STAGE0 1024
#define SMEMB  (SMEM_STAGE0 + STAGES * STAGEB)   // 99328 -> 2 CTAs/SM

#define NTILES   8192               // (MDIM/BM) * (NDIM/BN)
#define NCTA     296               // 2 per SM x 148 SMs

// barrier smem offsets
#define OFF_FULL  0      // 3 x 8B
#define OFF_EMPTY 64     // 3 x 8B

// pre-kernel grid split
#define X_TILES   (MDIM / BM * NKT)                // 4096 tiles
#define X_BLOCKS  ((size_t)X_TILES * 1024 / 256)   // 16384
#define W_TILES   (NDIM / BN * NKT)                // 512 tiles per batch
#define W_BLOCKS  ((size_t)W_TILES * 1024 / 256)   // 2048

// ======================= static fp16 scratch: TILED + PRE-SWIZZLED =======================
__device__ __align__(1024) unsigned char g_xh[(size_t)MDIM * KDIM * 2];              // 64 MB
__device__ __align__(1024) unsigned char g_wc[(size_t)NBATCH * NDIM * KDIM * 2];     // 128 MB

// ======================= small helpers =======================
__device__ __forceinline__ uint32_t h2_as_u32(__half2 h) {
    return *reinterpret_cast<uint32_t*>(&h);
}

__device__ __forceinline__ uint32_t smem_u32(const void* p) {
    uint32_t a;
    asm("{ .reg .u64 t; cvta.to.shared.u64 t, %1; cvt.u32.u64 %0, t; }" : "=r"(a) : "l"(p));
    return a;
}

#define SW128(o) ((o) ^ (((o) >> 3) & 0x70))

__device__ __forceinline__ void mbar_init(uint32_t bar, uint32_t cnt) {
    asm volatile("mbarrier.init.shared.b64 [%0], %1;" :: "r"(bar), "r"(cnt) : "memory");
}
__device__ __forceinline__ void mbar_arrive(uint32_t bar) {
    asm volatile("mbarrier.arrive.shared.b64 _, [%0];" :: "r"(bar) : "memory");
}
__device__ __forceinline__ void mbar_expect_tx(uint32_t bar, uint32_t bytes) {
    asm volatile("mbarrier.arrive.expect_tx.shared.b64 _, [%0], %1;" :: "r"(bar), "r"(bytes) : "memory");
}
__device__ __forceinline__ void mbar_wait(uint32_t bar, uint32_t parity) {
    asm volatile(
        "{\n\t"
        ".reg .pred P;\n\t"
        "WL_%=:\n\t"
        "mbarrier.try_wait.parity.acquire.cta.shared::cta.b64 P, [%0], %1, 0x989680;\n\t"
        "@P bra.uni WD_%=;\n\t"
        "bra.uni WL_%=;\n\t"
        "WD_%=:\n\t"
        "}"
        :: "r"(bar), "r"(parity) : "memory");
}
// 1D bulk async copy global->shared, completes via mbarrier tx (sm_90 baseline PTX)
__device__ __forceinline__ void bulk_g2s(uint32_t dst, const void* src, uint32_t bytes, uint32_t bar) {
    asm volatile(
        "cp.async.bulk.shared::cluster.global.mbarrier::complete_tx::bytes [%0], [%1], %2, [%3];"
        :: "r"(dst), "l"(src), "r"(bytes), "r"(bar) : "memory");
}

__device__ __forceinline__ void ldsm4(uint32_t* d, uint32_t addr) {
    asm volatile("ldmatrix.sync.aligned.m8n8.x4.shared.b16 {%0,%1,%2,%3}, [%4];"
                 : "=r"(d[0]), "=r"(d[1]), "=r"(d[2]), "=r"(d[3]) : "r"(addr));
}

__device__ __forceinline__ void mma16816(float* c, const uint32_t* a, uint32_t b0, uint32_t b1) {
    asm volatile(
        "mma.sync.aligned.m16n8k16.row.col.f32.f16.f16.f32 "
        "{%0,%1,%2,%3}, {%4,%5,%6,%7}, {%8,%9}, {%0,%1,%2,%3};"
        : "+f"(c[0]), "+f"(c[1]), "+f"(c[2]), "+f"(c[3])
        : "r"(a[0]), "r"(a[1]), "r"(a[2]), "r"(a[3]), "r"(b0), "r"(b1));
}

// ======================= fused pre-pass: convert + tile + swizzle (unchanged, proven) =======================
__global__ void __launch_bounds__(256) pre_kernel(const float* __restrict__ x,
                                                  const float* __restrict__ w,
                                                  const float* __restrict__ g,
                                                  const float* __restrict__ lr) {
    const int tid = threadIdx.x;
    if (blockIdx.x < X_BLOCKS) {
        size_t cid = (size_t)blockIdx.x * 256 + tid;       // 16B chunk id
        size_t tileIdx = cid >> 10;                        // 1024 chunks per tile
        int t  = (int)(cid & 1023);
        int r  = t >> 3, cc = t & 7;
        int mb = (int)(tileIdx >> 4), kt = (int)(tileIdx & 15);
        const float* src = x + ((size_t)mb * 128 + r) * KDIM + kt * 64 + cc * 8;
        float4 v0 = *reinterpret_cast<const float4*>(src);
        float4 v1 = *reinterpret_cast<const float4*>(src + 4);
        uint4 o;
        o.x = h2_as_u32(__floats2half2_rn(v0.x, v0.y));
        o.y = h2_as_u32(__floats2half2_rn(v0.z, v0.w));
        o.z = h2_as_u32(__floats2half2_rn(v1.x, v1.y));
        o.w = h2_as_u32(__floats2half2_rn(v1.z, v1.w));
        *reinterpret_cast<uint4*>(g_xh + tileIdx * TILEB + SW128(r * 128 + cc * 16)) = o;
    } else {
        size_t cid = (size_t)(blockIdx.x - X_BLOCKS) * 256 + tid;
        size_t tileIdx = cid >> 10;                                  // 0..511
        int t  = (int)(cid & 1023);
        int r  = t >> 3, cc = t & 7;
        int nb = (int)(tileIdx >> 4), kt = (int)(tileIdx & 15);
        const size_t soff = ((size_t)nb * 128 + r) * KDIM + kt * 64 + cc * 8;
        float4 vw0 = *reinterpret_cast<const float4*>(w + soff);
        float4 vw1 = *reinterpret_cast<const float4*>(w + soff + 4);
        float4 vg0 = *reinterpret_cast<const float4*>(g + soff);
        float4 vg1 = *reinterpret_cast<const float4*>(g + soff + 4);
        const uint32_t swoff = SW128(r * 128 + cc * 16);
        #pragma unroll
        for (int b = 0; b < NBATCH; ++b) {
            float l = __ldg(lr + b);
            uint4 o;
            o.x = h2_as_u32(__floats2half2_rn(vw0.x - l * vg0.x, vw0.y - l * vg0.y));
            o.y = h2_as_u32(__floats2half2_rn(vw0.z - l * vg0.z, vw0.w - l * vg0.w));
            o.z = h2_as_u32(__floats2half2_rn(vw1.x - l * vg1.x, vw1.y - l * vg1.y));
            o.w = h2_as_u32(__floats2half2_rn(vw1.z - l * vg1.z, vw1.w - l * vg1.w));
            *reinterpret_cast<uint4*>(g_wc + ((size_t)b * W_TILES + tileIdx) * TILEB + swoff) = o;
        }
    }
}

// ======================= persistent GEMM kernel =======================
// 296 persistent CTAs, 128 threads = 4 warps (2x2), warp tile 64x64 (the proven R6 consumer).
// Continuous ktile counter kk rolls across tiles: stage slots/parities never reset,
// so the pipeline stays warm through tile transitions and the epilogue overlaps refills.

// producer fill for this CTA's local ktile kk (tile index bid + (kk>>4)*NCTA)
__device__ __forceinline__ void fill_kk(uint32_t sb, int bid, int kk, uint32_t full_bar) {
    const int tg = bid + (kk >> 4) * NCTA;     // global tile id
    const int kt = kk & 15;
    const int mb = tg >> 5, nb = tg & 31;
    const unsigned char* srcA = g_xh + ((size_t)(mb * NKT + kt)) * TILEB;
    const unsigned char* srcB = g_wc + ((size_t)((mb >> 4) * W_TILES + nb * NKT + kt)) * TILEB;
    const uint32_t dst = sb + SMEM_STAGE0 + (uint32_t)(kk % STAGES) * STAGEB;
    mbar_expect_tx(full_bar, STAGEB);
    bulk_g2s(dst,         srcA, TILEB, full_bar);
    bulk_g2s(dst + TILEB, srcB, TILEB, full_bar);
}

__global__ void __launch_bounds__(128, 2) gemm_kernel(const float* __restrict__ bias,
                                                      const float* __restrict__ gbias,
                                                      const float* __restrict__ lr_arr,
                                                      float* __restrict__ out) {
    extern __shared__ char smem[];
    const uint32_t sb = smem_u32(smem);
    const int tid  = threadIdx.x;
    const int warp = tid >> 5, lane = tid & 31;
    const int warp_m = (warp & 1) * 64;
    const int warp_n = (warp >> 1) * 64;
    const int bid = blockIdx.x;

    // this CTA's tile count: tiles bid, bid+NCTA, ... < NTILES
    const int ntl  = (NTILES - bid + NCTA - 1) / NCTA;
    const int TOTK = ntl * NKT;

    const uint32_t full_b  = sb + OFF_FULL;
    const uint32_t empty_b = sb + OFF_EMPTY;

    if (tid == 0) {
        #pragma unroll
        for (int s = 0; s < STAGES; ++s) {
            mbar_init(full_b + s * 8, 1);
            mbar_init(empty_b + s * 8, 128);
        }
    }
    __syncthreads();

    // prologue: tid 0 fills all 3 stages (kk = 0,1,2)
    if (tid == 0) {
        #pragma unroll
        for (int p = 0; p < STAGES; ++p)
            fill_kk(sb, bid, p, full_b + p * 8);
    }

    // ldsm lane addressing (stage-relative, swizzled) — exact R6
    const int a_row  = warp_m + (lane & 15);
    const int a_colb = (lane >> 4) * 16;
    const int b_row  = warp_n + ((lane >> 4) * 8 + (lane & 7));
    const int b_colb = ((lane >> 3) & 1) * 16;

    float acc[4][8][4];
    #pragma unroll
    for (int i = 0; i < 4; ++i)
        #pragma unroll
        for (int j = 0; j < 8; ++j)
            #pragma unroll
            for (int t = 0; t < 4; ++t) acc[i][j][t] = 0.0f;

    uint32_t afr[2][4][4], bfr[2][4][4];

    for (int kk = 0; kk < TOTK; ++kk) {
        const int s = kk % STAGES;
        const uint32_t phase = (uint32_t)((kk / STAGES) & 1);
        mbar_wait(full_b + s * 8, phase);

        const uint32_t Ab = sb + SMEM_STAGE0 + s * STAGEB;
        const uint32_t Bb = Ab + TILEB;

        // prime fragments for ks = 0 (exact R6 body)
        #pragma unroll
        for (int mf = 0; mf < 4; ++mf)
            ldsm4(afr[0][mf], Ab + SW128((a_row + mf * 16) * 128 + a_colb));
        #pragma unroll
        for (int np = 0; np < 4; ++np)
            ldsm4(bfr[0][np], Bb + SW128((b_row + np * 16) * 128 + b_colb));

        #pragma unroll
        for (int ks = 0; ks < 4; ++ks) {
            const int cur = ks & 1, nxtb = cur ^ 1;
            if (ks < 3) {
                const int kb = (ks + 1) * 32;
                #pragma unroll
                for (int mf = 0; mf < 4; ++mf)
                    ldsm4(afr[nxtb][mf], Ab + SW128((a_row + mf * 16) * 128 + kb + a_colb));
                #pragma unroll
                for (int np = 0; np < 4; ++np)
                    ldsm4(bfr[nxtb][np], Bb + SW128((b_row + np * 16) * 128 + kb + b_colb));
            }
            #pragma unroll
            for (int mf = 0; mf < 4; ++mf) {
                #pragma unroll
                for (int np = 0; np < 4; ++np) {
                    mma16816(acc[mf][2 * np],     afr[cur][mf], bfr[cur][np][0], bfr[cur][np][1]);
                    mma16816(acc[mf][2 * np + 1], afr[cur][mf], bfr[cur][np][2], bfr[cur][np][3]);
                }
            }
        }

        // release stage; tid 0 refills it for kk+3 (may belong to the NEXT tile)
        mbar_arrive(empty_b + s * 8);
        if (tid == 0 && kk + STAGES < TOTK) {
            mbar_wait(empty_b + s * 8, phase);
            fill_kk(sb, bid, kk + STAGES, full_b + s * 8);
        }

        // ---------- per-tile epilogue (no smem, overlaps the live pipeline) ----------
        if ((kk & 15) == 15) {
            const int tg = bid + (kk >> 4) * NCTA;
            const int mb = tg >> 5, nb = tg & 31;
            const int rowA0 = mb * BM;
            const int colB0 = nb * BN;
            const float lr = __ldg(lr_arr + (mb >> 4));

            // combined bias per nf (reused across all 4 mf)
            float bc[8][2];
            #pragma unroll
            for (int nf = 0; nf < 8; ++nf) {
                const int cl = colB0 + warp_n + nf * 8 + (lane & 3) * 2;
                bc[nf][0] = __ldg(bias + cl)     - lr * __ldg(gbias + cl);
                bc[nf][1] = __ldg(bias + cl + 1) - lr * __ldg(gbias + cl + 1);
            }

            #pragma unroll
            for (int mf = 0; mf < 4; ++mf) {
                const int gr0 = rowA0 + warp_m + mf * 16 + (lane >> 2);
                #pragma unroll
                for (int nf = 0; nf < 8; ++nf) {
                    const int cl = colB0 + warp_n + nf * 8 + (lane & 3) * 2;
                    float2 v0 = make_float2(acc[mf][nf][0] + bc[nf][0], acc[mf][nf][1] + bc[nf][1]);
                    float2 v1 = make_float2(acc[mf][nf][2] + bc[nf][0], acc[mf][nf][3] + bc[nf][1]);
                    *reinterpret_cast<float2*>(out + (size_t)gr0 * NDIM + cl)       = v0;
                    *reinterpret_cast<float2*>(out + (size_t)(gr0 + 8) * NDIM + cl) = v1;
                    acc[mf][nf][0] = 0.0f; acc[mf][nf][1] = 0.0f;
                    acc[mf][nf][2] = 0.0f; acc[mf][nf][3] = 0.0f;
                }
            }
        }
    }
}

// ======================= launch =======================
extern "C" void kernel_launch(void* const* d_in, const int* in_sizes, int n_in,
                              void* d_out, int out_size) {
    (void)in_sizes; (void)n_in; (void)out_size;
    const float* x    = (const float*)d_in[0];
    const float* w    = (const float*)d_in[1];
    const float* bias = (const float*)d_in[2];
    const float* g    = (const float*)d_in[3];
    const float* gb   = (const float*)d_in[4];
    const float* lr   = (const float*)d_in[5];
    float* out = (float*)d_out;

    static bool attr_set = false;
    if (!attr_set) {
        cudaFuncSetAttribute(gemm_kernel, cudaFuncAttributeMaxDynamicSharedMemorySize, SMEMB);
        attr_set = true;
    }

    pre_kernel<<<(unsigned)(X_BLOCKS + W_BLOCKS), 256>>>(x, w, g, lr);
    gemm_kernel<<<NCTA, 128, SMEMB>>>(bias, gb, lr, out);
}